// round 15
// baseline (speedup 1.0000x reference)
#include <cuda_runtime.h>
#include <cuda_fp16.h>
#include <cstdint>

#define B_ 2
#define S_ 2048
#define D_ 1024
#define H_ 16
#define HD_ 64
#define N_ (B_*S_)

// ---------------- scratch ----------------
__device__ __half g_I[3][(size_t)N_*D_];          // inputs fp16
__device__ __half g_W[4][(size_t)D_*D_];          // transposed weights fp16
__device__ __half g_Q[(size_t)N_*D_];             // [B,H,S,HD] fp16 (scaled by log2e/8)
__device__ __half g_K[(size_t)N_*D_];             // [B,H,S,HD] fp16
__device__ __half g_V[(size_t)N_*D_];             // [B,H,HD,S] fp16
__device__ __half g_C[(size_t)N_*D_];             // ctx fp16 [B,S,D]

// ---------------- helpers ----------------
__device__ __forceinline__ uint32_t smem_u32(const void* p){
  uint32_t a; asm("{.reg .u64 t; cvta.to.shared.u64 t,%1; cvt.u32.u64 %0,t;}":"=r"(a):"l"(p)); return a;
}
__device__ __forceinline__ uint32_t packh2(float f0, float f1){
  uint32_t r; asm("cvt.rn.f16x2.f32 %0,%1,%2;":"=r"(r):"f"(f1),"f"(f0)); return r;
}
__device__ __forceinline__ uint32_t ex2h2(uint32_t a){
  uint32_t d; asm("ex2.approx.f16x2 %0,%1;":"=r"(d):"r"(a)); return d;
}
__device__ __forceinline__ void mma_f16(float* c, const uint32_t* a, const uint32_t* b){
  asm volatile("mma.sync.aligned.m16n8k16.row.col.f32.f16.f16.f32 "
    "{%0,%1,%2,%3},{%4,%5,%6,%7},{%8,%9},{%0,%1,%2,%3};"
    : "+f"(c[0]),"+f"(c[1]),"+f"(c[2]),"+f"(c[3])
    : "r"(a[0]),"r"(a[1]),"r"(a[2]),"r"(a[3]),"r"(b[0]),"r"(b[1]));
}
__device__ __forceinline__ void ldsm4(uint32_t* r, uint32_t a){
  asm volatile("ldmatrix.sync.aligned.m8n8.x4.shared.b16 {%0,%1,%2,%3},[%4];"
    : "=r"(r[0]),"=r"(r[1]),"=r"(r[2]),"=r"(r[3]) : "r"(a));
}
__device__ __forceinline__ void cpa16(uint32_t s, const void* g){
  asm volatile("cp.async.cg.shared.global [%0],[%1],16;"::"r"(s),"l"(g):"memory");
}
#define CPA_COMMIT() asm volatile("cp.async.commit_group;":::"memory")
#define CPA_WAIT(n)  asm volatile("cp.async.wait_group %0;"::"n"(n):"memory")

// ---------------- prep: convert activations to fp16 ----------------
__global__ __launch_bounds__(256) void cvt_act(
  const float* __restrict__ a, const float* __restrict__ b, const float* __restrict__ c,
  __half* __restrict__ o)
{
  int y = blockIdx.y;
  const float* src = (y==0)?a:(y==1)?b:c;
  size_t i = (size_t)blockIdx.x*256 + threadIdx.x;
  float2 v = ((const float2*)src)[i];
  ((uint32_t*)(o + (size_t)y*N_*D_))[i] = packh2(v.x, v.y);
}

// ---------------- prep: transpose weights to fp16 ----------------
__global__ __launch_bounds__(256) void wsplit(
  const float* __restrict__ w0,const float* __restrict__ w1,
  const float* __restrict__ w2,const float* __restrict__ w3,
  __half* __restrict__ wt)
{
  __shared__ float t[32][33];
  const float* src=(blockIdx.z==0)?w0:(blockIdx.z==1)?w1:(blockIdx.z==2)?w2:w3;
  size_t base=(size_t)blockIdx.z*D_*D_;
  int tx=threadIdx.x, ty=threadIdx.y, kb=blockIdx.y*32, nb=blockIdx.x*32;
#pragma unroll
  for(int i=0;i<32;i+=8) t[ty+i][tx]=src[(size_t)(kb+ty+i)*D_+nb+tx];
  __syncthreads();
#pragma unroll
  for(int i=0;i<32;i+=8)
    wt[base+(size_t)(nb+ty+i)*D_+kb+tx]=__float2half(t[tx][ty+i]);
}

// ---------------- GEMM: R13 config (K-chunk 64, pair-packed B, 3 stages) ----
#define GSTG 36864
#define G_SMEM (3*GSTG)   // 110592

__device__ __forceinline__ void gemm_core(
  const __half* __restrict__ X, const __half* __restrict__ W,
  int bm, int bn, uint32_t smb, float acc[4][4][4])
{
  const int tid=threadIdx.x, lane=tid&31, wid=tid>>5;
  const int wm=wid>>2, wn=wid&3;
  const uint32_t arow=(lane&7)+8*((lane>>3)&1), akof=(lane>>4)*8;
  const uint32_t bprow=((lane>>4)&1)*8+(lane&7), bpk=((lane>>3)&1)*8;

  auto ld=[&](int c,int s){
    const __half* xp=X+(size_t)bm*D_+c*64;
    const __half* wp=W+(size_t)bn*D_+c*64;
#pragma unroll
    for(int t=tid;t<1024;t+=256){
      int r=t>>3, sg=t&7;
      uint32_t d=smb+s*GSTG+r*144+sg*16;
      const size_t go=(size_t)r*D_+sg*8;
      cpa16(d,       xp+go);
      cpa16(d+18432, wp+go);
    }
  };

#pragma unroll
  for(int i=0;i<4;i++)
#pragma unroll
    for(int j=0;j<4;j++)
#pragma unroll
      for(int r=0;r<4;r++) acc[i][j][r]=0.f;

  ld(0,0); CPA_COMMIT();
  ld(1,1); CPA_COMMIT();

  for(int c=0;c<16;c++){
    if(c<15){ CPA_WAIT(1); } else { CPA_WAIT(0); }
    __syncthreads();
    const uint32_t base=smb+(c%3)*GSTG;
#pragma unroll
    for(int h=0;h<4;h++){
      uint32_t a4[4][4];
#pragma unroll
      for(int mi=0;mi<4;mi++){
        uint32_t ad=base+(wm*64+mi*16+arow)*144+(h*16+akof)*2;
        ldsm4(a4[mi],ad);
      }
      uint32_t bp0[4], bp1[4];
      {
        uint32_t ad=base+18432+(wn*32+bprow)*144+(h*16+bpk)*2;
        ldsm4(bp0,ad);
        ldsm4(bp1,ad+16*144);
      }
#pragma unroll
      for(int mi=0;mi<4;mi++){
        mma_f16(acc[mi][0], a4[mi], &bp0[0]);
        mma_f16(acc[mi][1], a4[mi], &bp0[2]);
        mma_f16(acc[mi][2], a4[mi], &bp1[0]);
        mma_f16(acc[mi][3], a4[mi], &bp1[2]);
      }
    }
    if(c+2<16){ ld(c+2,(c+2)%3); CPA_COMMIT(); }
  }
}

// ---------------- fused QKV projection ----------------
__global__ __launch_bounds__(256,2) void gemm_qkv(
  const __half* __restrict__ I, const __half* __restrict__ Wt,
  const float* __restrict__ bq, const float* __restrict__ bk, const float* __restrict__ bv,
  __half* __restrict__ qq, __half* __restrict__ kk, __half* __restrict__ vv)
{
  extern __shared__ char sm[];
  const uint32_t smb = smem_u32(sm);
  const int z=blockIdx.z;
  const size_t P=(size_t)N_*D_, W=(size_t)D_*D_;
  const __half* Xp=I+(size_t)z*P;
  const __half* Wp=Wt+(size_t)z*W;
  const float* bias=(z==0)?bq:(z==1)?bk:bv;
  const float scale=(z==0)?(0.125f*1.4426950408889634f):1.0f;
  const int bm=blockIdx.y*128, bn=blockIdx.x*128;

  float acc[4][4][4];
  gemm_core(Xp,Wp,bm,bn,smb,acc);

  const int tid=threadIdx.x, lane=tid&31, wid=tid>>5;
  const int wm=wid>>2, wn=wid&3;
  const int g=lane>>2, tg=lane&3;
#pragma unroll
  for(int mi=0;mi<4;mi++){
    const int m0=bm+wm*64+mi*16+g;
#pragma unroll
    for(int ni=0;ni<4;ni++){
      const int n0=bn+wn*32+ni*8+2*tg;
      const float2 bb=*(const float2*)&bias[n0];
      float v00=(acc[mi][ni][0]+bb.x)*scale, v01=(acc[mi][ni][1]+bb.y)*scale;
      float v10=(acc[mi][ni][2]+bb.x)*scale, v11=(acc[mi][ni][3]+bb.y)*scale;
      const int h=n0>>6, hd=n0&63;
      if(z<2){
        __half* dst=(z==0)?qq:kk;
#pragma unroll
        for(int rr=0;rr<2;rr++){
          const int m=m0+rr*8, b=m>>11, s=m&(S_-1);
          const size_t idx=(((size_t)(b*H_+h)*S_)+s)*HD_+hd;
          *(uint32_t*)&dst[idx]=packh2(rr?v10:v00, rr?v11:v01);
        }
      } else {
#pragma unroll
        for(int rr=0;rr<2;rr++){
          const int m=m0+rr*8, b=m>>11, s=m&(S_-1);
#pragma unroll
          for(int e=0;e<2;e++){
            const int n=n0+e, hh=n>>6, hhd=n&63;
            float v = rr ? (e?v11:v10) : (e?v01:v00);
            vv[(((size_t)(b*H_+hh)*HD_)+hhd)*S_+s]=__float2half(v);
          }
        }
      }
    }
  }
}

// ---------------- fc GEMM (fp32 out) ----------------
__global__ __launch_bounds__(256,2) void gemm_fc(
  const __half* __restrict__ X, const __half* __restrict__ W,
  const float* __restrict__ bias, float* __restrict__ outf)
{
  extern __shared__ char sm[];
  const uint32_t smb = smem_u32(sm);
  const int bm=blockIdx.y*128, bn=blockIdx.x*128;

  float acc[4][4][4];
  gemm_core(X,W,bm,bn,smb,acc);

  const int tid=threadIdx.x, lane=tid&31, wid=tid>>5;
  const int wm=wid>>2, wn=wid&3;
  const int g=lane>>2, tg=lane&3;
#pragma unroll
  for(int mi=0;mi<4;mi++){
    const int m0=bm+wm*64+mi*16+g;
#pragma unroll
    for(int ni=0;ni<4;ni++){
      const int n0=bn+wn*32+ni*8+2*tg;
      const float2 bb=*(const float2*)&bias[n0];
      float2 w0={acc[mi][ni][0]+bb.x, acc[mi][ni][1]+bb.y};
      float2 w1={acc[mi][ni][2]+bb.x, acc[mi][ni][3]+bb.y};
      *(float2*)&outf[(size_t)m0*D_+n0]=w0;
      *(float2*)&outf[(size_t)(m0+8)*D_+n0]=w1;
    }
  }
}

// ---------------- flash attention: software-pipelined S/PV -----------------
// 256 thr, warp tile 32q x 64keys, Q persistent; S(i+1) overlapped with PV(i).
// smem: Q[256][72] | 4 stages of { K[64][72], V[64][72] }
#define AQSZ  36864
#define ASTGn 18432
#define A_SMEM (AQSZ + 4*ASTGn)   // 110592

__global__ __launch_bounds__(256,1) void attn(
  const __half* __restrict__ Q, const __half* __restrict__ K,
  const __half* __restrict__ V, __half* __restrict__ C)
{
  extern __shared__ char sm[];
  const uint32_t smb=smem_u32(sm);
  const int tid=threadIdx.x, lane=tid&31, wid=tid>>5;
  const int bh=blockIdx.y, q0=blockIdx.x*256;

  const uint32_t arow=(lane&7)+8*((lane>>3)&1), akof=(lane>>4)*8;
  const uint32_t brow=lane&7, bkof=(lane>>3)*8;
  const uint32_t ones2[2]={0x3C003C00u,0x3C003C00u};

  auto ldt=[&](int i,int s){
    const __half* kp=K+((size_t)bh*S_+i*64)*HD_;
    const __half* vp=V+(size_t)bh*HD_*S_+i*64;
    const uint32_t sb=smb+AQSZ+s*ASTGn;
#pragma unroll
    for(int t=tid;t<512;t+=256){
      int r=t>>3, sg=t&7;
      cpa16(sb+r*144+sg*16,      kp+(size_t)r*HD_+sg*8);
      cpa16(sb+9216+r*144+sg*16, vp+(size_t)r*S_+sg*8);
    }
  };

  // prologue: Q (256 rows, persistent) + tiles 0..2
  {
    const __half* qp=Q+((size_t)bh*S_+q0)*HD_;
#pragma unroll
    for(int t=tid;t<2048;t+=256){
      int r=t>>3, sg=t&7;
      cpa16(smb+r*144+sg*16, qp+(size_t)r*HD_+sg*8);
    }
    CPA_COMMIT();
  }
  ldt(0,0); CPA_COMMIT();
  ldt(1,1); CPA_COMMIT();
  ldt(2,2); CPA_COMMIT();

  // persistent Q fragments (after Q group completes)
  CPA_WAIT(3);
  __syncthreads();
  uint32_t qf[2][4][4];
#pragma unroll
  for(int mi=0;mi<2;mi++)
#pragma unroll
    for(int ks=0;ks<4;ks++){
      uint32_t ad=smb+(wid*32+mi*16+arow)*144+(ks*16+akof)*2;
      ldsm4(qf[mi][ks],ad);
    }

  float oacc[2][8][4];
#pragma unroll
  for(int mi=0;mi<2;mi++)
#pragma unroll
    for(int i=0;i<8;i++)
#pragma unroll
      for(int r=0;r<4;r++) oacc[mi][i][r]=0.f;
  float lacc[2][4]={{0.f,0.f,0.f,0.f},{0.f,0.f,0.f,0.f}};

  // S(0) out of the loop
  float sacc[2][8][4];
  CPA_WAIT(2);
  __syncthreads();
#pragma unroll
  for(int mi=0;mi<2;mi++)
#pragma unroll
    for(int ni=0;ni<8;ni++)
#pragma unroll
      for(int r=0;r<4;r++) sacc[mi][ni][r]=0.f;
  {
    const uint32_t kb=smb+AQSZ;   // stage 0
#pragma unroll
    for(int kp=0;kp<2;kp++)
#pragma unroll
      for(int ni=0;ni<8;ni++){
        uint32_t ad=kb+(ni*8+brow)*144+(kp*32+bkof)*2;
        uint32_t kf[4]; ldsm4(kf,ad);
#pragma unroll
        for(int mi=0;mi<2;mi++){
          mma_f16(sacc[mi][ni], qf[mi][2*kp],   &kf[0]);
          mma_f16(sacc[mi][ni], qf[mi][2*kp+1], &kf[2]);
        }
      }
  }

  for(int i=0;i<32;i++){
    if(i<30){ CPA_WAIT(1); } else { CPA_WAIT(0); }
    __syncthreads();
    const uint32_t vb=smb+AQSZ+(i&3)*ASTGn;
    const uint32_t kb=smb+AQSZ+((i+1)&3)*ASTGn;

    // P(i) = 2^(sacc) for all 64 keys; row-sums via ones-mma
    uint32_t pp[2][2][2][4];   // [kp][half][mi][4]
#pragma unroll
    for(int kp=0;kp<2;kp++)
#pragma unroll
      for(int mi=0;mi<2;mi++){
        const int j0=4*kp;
        pp[kp][0][mi][0]=ex2h2(packh2(sacc[mi][j0  ][0],sacc[mi][j0  ][1]));
        pp[kp][0][mi][1]=ex2h2(packh2(sacc[mi][j0  ][2],sacc[mi][j0  ][3]));
        pp[kp][0][mi][2]=ex2h2(packh2(sacc[mi][j0+1][0],sacc[mi][j0+1][1]));
        pp[kp][0][mi][3]=ex2h2(packh2(sacc[mi][j0+1][2],sacc[mi][j0+1][3]));
        pp[kp][1][mi][0]=ex2h2(packh2(sacc[mi][j0+2][0],sacc[mi][j0+2][1]));
        pp[kp][1][mi][1]=ex2h2(packh2(sacc[mi][j0+2][2],sacc[mi][j0+2][3]));
        pp[kp][1][mi][2]=ex2h2(packh2(sacc[mi][j0+3][0],sacc[mi][j0+3][1]));
        pp[kp][1][mi][3]=ex2h2(packh2(sacc[mi][j0+3][2],sacc[mi][j0+3][3]));
        mma_f16(lacc[mi], pp[kp][0][mi], ones2);
        mma_f16(lacc[mi], pp[kp][1][mi], ones2);
      }

    // S(i+1): independent mma stream, overlaps the ex2 chain above
    if(i<31){
#pragma unroll
      for(int mi=0;mi<2;mi++)
#pragma unroll
        for(int ni=0;ni<8;ni++)
#pragma unroll
          for(int r=0;r<4;r++) sacc[mi][ni][r]=0.f;
#pragma unroll
      for(int kp=0;kp<2;kp++)
#pragma unroll
        for(int ni=0;ni<8;ni++){
          uint32_t ad=kb+(ni*8+brow)*144+(kp*32+bkof)*2;
          uint32_t kf[4]; ldsm4(kf,ad);
#pragma unroll
          for(int mi=0;mi<2;mi++){
            mma_f16(sacc[mi][ni], qf[mi][2*kp],   &kf[0]);
            mma_f16(sacc[mi][ni], qf[mi][2*kp+1], &kf[2]);
          }
        }
    }

    // O += P(i) V(i)
#pragma unroll
    for(int kp=0;kp<2;kp++)
#pragma unroll
      for(int ni=0;ni<8;ni++){
        uint32_t ad=vb+9216+(ni*8+brow)*144+(kp*32+bkof)*2;
        uint32_t vf[4]; ldsm4(vf,ad);
#pragma unroll
        for(int mi=0;mi<2;mi++){
          mma_f16(oacc[mi][ni], pp[kp][0][mi], &vf[0]);
          mma_f16(oacc[mi][ni], pp[kp][1][mi], &vf[2]);
        }
      }

    if(i+3<32){ ldt(i+3,(i+3)&3); CPA_COMMIT(); }
  }

  const int g=lane>>2, tg=lane&3;
  const int b=bh>>4, h=bh&15;
#pragma unroll
  for(int mi=0;mi<2;mi++){
    const float inv0=1.f/lacc[mi][0], inv1=1.f/lacc[mi][2];
    const int r0=q0+wid*32+mi*16+g;
#pragma unroll
    for(int ni=0;ni<8;ni++){
      const int d=ni*8+2*tg;
      size_t idx=((size_t)(b*S_+r0))*D_+h*HD_+d;
      *(uint32_t*)&C[idx]=packh2(oacc[mi][ni][0]*inv0, oacc[mi][ni][1]*inv0);
      idx=((size_t)(b*S_+r0+8))*D_+h*HD_+d;
      *(uint32_t*)&C[idx]=packh2(oacc[mi][ni][2]*inv1, oacc[mi][ni][3]*inv1);
    }
  }
}

// ---------------- launch ----------------
extern "C" void kernel_launch(void* const* d_in, const int* in_sizes, int n_in,
                              void* d_out, int out_size)
{
  const float* query=(const float*)d_in[0];
  const float* key  =(const float*)d_in[1];
  const float* value=(const float*)d_in[2];
  const float* w_q=(const float*)d_in[3];  const float* b_q=(const float*)d_in[4];
  const float* w_k=(const float*)d_in[5];  const float* b_k=(const float*)d_in[6];
  const float* w_v=(const float*)d_in[7];  const float* b_v=(const float*)d_in[8];
  const float* w_fc=(const float*)d_in[9]; const float* b_fc=(const float*)d_in[10];
  float* out=(float*)d_out;

  __half *pI,*pW,*pQ,*pK,*pV,*pC;
  cudaGetSymbolAddress((void**)&pI,g_I);
  cudaGetSymbolAddress((void**)&pW,g_W);
  cudaGetSymbolAddress((void**)&pQ,g_Q); cudaGetSymbolAddress((void**)&pK,g_K);
  cudaGetSymbolAddress((void**)&pV,g_V); cudaGetSymbolAddress((void**)&pC,g_C);

  cudaFuncSetAttribute(gemm_qkv,cudaFuncAttributeMaxDynamicSharedMemorySize,G_SMEM);
  cudaFuncSetAttribute(gemm_fc, cudaFuncAttributeMaxDynamicSharedMemorySize,G_SMEM);
  cudaFuncSetAttribute(attn,    cudaFuncAttributeMaxDynamicSharedMemorySize,A_SMEM);

  cvt_act<<<dim3((N_*D_/2)/256,3),256>>>(query,key,value,pI);
  wsplit<<<dim3(32,32,4),dim3(32,8)>>>(w_q,w_k,w_v,w_fc,pW);

  const size_t W=(size_t)D_*D_;
  gemm_qkv<<<dim3(8,32,3),256,G_SMEM>>>(pI,pW,b_q,b_k,b_v,pQ,pK,pV);

  attn<<<dim3(8,32),256,A_SMEM>>>(pQ,pK,pV,pC);

  gemm_fc<<<dim3(8,32),256,G_SMEM>>>(pC,pW+3*W,b_fc,out);
}

// round 16
// speedup vs baseline: 1.0804x; 1.0804x over previous
#include <cuda_runtime.h>
#include <cuda_fp16.h>
#include <cstdint>

#define B_ 2
#define S_ 2048
#define D_ 1024
#define H_ 16
#define HD_ 64
#define N_ (B_*S_)

// ---------------- scratch ----------------
__device__ __half g_I[3][(size_t)N_*D_];          // inputs fp16
__device__ __half g_W[4][(size_t)D_*D_];          // transposed weights fp16
__device__ __half g_Q[(size_t)N_*D_];             // [B,H,S,HD] fp16 (scaled by log2e/8)
__device__ __half g_K[(size_t)N_*D_];             // [B,H,S,HD] fp16
__device__ __half g_V[(size_t)N_*D_];             // [B,H,HD,S] fp16
__device__ __half g_C[(size_t)N_*D_];             // ctx fp16 [B,S,D]

// ---------------- helpers ----------------
__device__ __forceinline__ uint32_t smem_u32(const void* p){
  uint32_t a; asm("{.reg .u64 t; cvta.to.shared.u64 t,%1; cvt.u32.u64 %0,t;}":"=r"(a):"l"(p)); return a;
}
__device__ __forceinline__ uint32_t packh2(float f0, float f1){
  uint32_t r; asm("cvt.rn.f16x2.f32 %0,%1,%2;":"=r"(r):"f"(f1),"f"(f0)); return r;
}
__device__ __forceinline__ uint32_t ex2h2(uint32_t a){
  uint32_t d; asm("ex2.approx.f16x2 %0,%1;":"=r"(d):"r"(a)); return d;
}
__device__ __forceinline__ void mma_f16(float* c, const uint32_t* a, const uint32_t* b){
  asm volatile("mma.sync.aligned.m16n8k16.row.col.f32.f16.f16.f32 "
    "{%0,%1,%2,%3},{%4,%5,%6,%7},{%8,%9},{%0,%1,%2,%3};"
    : "+f"(c[0]),"+f"(c[1]),"+f"(c[2]),"+f"(c[3])
    : "r"(a[0]),"r"(a[1]),"r"(a[2]),"r"(a[3]),"r"(b[0]),"r"(b[1]));
}
__device__ __forceinline__ void ldsm4(uint32_t* r, uint32_t a){
  asm volatile("ldmatrix.sync.aligned.m8n8.x4.shared.b16 {%0,%1,%2,%3},[%4];"
    : "=r"(r[0]),"=r"(r[1]),"=r"(r[2]),"=r"(r[3]) : "r"(a));
}
__device__ __forceinline__ void cpa16(uint32_t s, const void* g){
  asm volatile("cp.async.cg.shared.global [%0],[%1],16;"::"r"(s),"l"(g):"memory");
}
#define CPA_COMMIT() asm volatile("cp.async.commit_group;":::"memory")
#define CPA_WAIT(n)  asm volatile("cp.async.wait_group %0;"::"n"(n):"memory")

// ---------------- prep: convert activations to fp16 ----------------
__global__ __launch_bounds__(256) void cvt_act(
  const float* __restrict__ a, const float* __restrict__ b, const float* __restrict__ c,
  __half* __restrict__ o)
{
  int y = blockIdx.y;
  const float* src = (y==0)?a:(y==1)?b:c;
  size_t i = (size_t)blockIdx.x*256 + threadIdx.x;
  float2 v = ((const float2*)src)[i];
  ((uint32_t*)(o + (size_t)y*N_*D_))[i] = packh2(v.x, v.y);
}

// ---------------- prep: transpose weights to fp16 ----------------
__global__ __launch_bounds__(256) void wsplit(
  const float* __restrict__ w0,const float* __restrict__ w1,
  const float* __restrict__ w2,const float* __restrict__ w3,
  __half* __restrict__ wt)
{
  __shared__ float t[32][33];
  const float* src=(blockIdx.z==0)?w0:(blockIdx.z==1)?w1:(blockIdx.z==2)?w2:w3;
  size_t base=(size_t)blockIdx.z*D_*D_;
  int tx=threadIdx.x, ty=threadIdx.y, kb=blockIdx.y*32, nb=blockIdx.x*32;
#pragma unroll
  for(int i=0;i<32;i+=8) t[ty+i][tx]=src[(size_t)(kb+ty+i)*D_+nb+tx];
  __syncthreads();
#pragma unroll
  for(int i=0;i<32;i+=8)
    wt[base+(size_t)(nb+ty+i)*D_+kb+tx]=__float2half(t[tx][ty+i]);
}

// ---------------- GEMM: R13 config (K-chunk 64, pair-packed B, 3 stages) ----
#define GSTG 36864
#define G_SMEM (3*GSTG)   // 110592

__device__ __forceinline__ void gemm_core(
  const __half* __restrict__ X, const __half* __restrict__ W,
  int bm, int bn, uint32_t smb, float acc[4][4][4])
{
  const int tid=threadIdx.x, lane=tid&31, wid=tid>>5;
  const int wm=wid>>2, wn=wid&3;
  const uint32_t arow=(lane&7)+8*((lane>>3)&1), akof=(lane>>4)*8;
  const uint32_t bprow=((lane>>4)&1)*8+(lane&7), bpk=((lane>>3)&1)*8;

  auto ld=[&](int c,int s){
    const __half* xp=X+(size_t)bm*D_+c*64;
    const __half* wp=W+(size_t)bn*D_+c*64;
#pragma unroll
    for(int t=tid;t<1024;t+=256){
      int r=t>>3, sg=t&7;
      uint32_t d=smb+s*GSTG+r*144+sg*16;
      const size_t go=(size_t)r*D_+sg*8;
      cpa16(d,       xp+go);
      cpa16(d+18432, wp+go);
    }
  };

#pragma unroll
  for(int i=0;i<4;i++)
#pragma unroll
    for(int j=0;j<4;j++)
#pragma unroll
      for(int r=0;r<4;r++) acc[i][j][r]=0.f;

  ld(0,0); CPA_COMMIT();
  ld(1,1); CPA_COMMIT();

  for(int c=0;c<16;c++){
    if(c<15){ CPA_WAIT(1); } else { CPA_WAIT(0); }
    __syncthreads();
    const uint32_t base=smb+(c%3)*GSTG;
#pragma unroll
    for(int h=0;h<4;h++){
      uint32_t a4[4][4];
#pragma unroll
      for(int mi=0;mi<4;mi++){
        uint32_t ad=base+(wm*64+mi*16+arow)*144+(h*16+akof)*2;
        ldsm4(a4[mi],ad);
      }
      uint32_t bp0[4], bp1[4];
      {
        uint32_t ad=base+18432+(wn*32+bprow)*144+(h*16+bpk)*2;
        ldsm4(bp0,ad);
        ldsm4(bp1,ad+16*144);
      }
#pragma unroll
      for(int mi=0;mi<4;mi++){
        mma_f16(acc[mi][0], a4[mi], &bp0[0]);
        mma_f16(acc[mi][1], a4[mi], &bp0[2]);
        mma_f16(acc[mi][2], a4[mi], &bp1[0]);
        mma_f16(acc[mi][3], a4[mi], &bp1[2]);
      }
    }
    if(c+2<16){ ld(c+2,(c+2)%3); CPA_COMMIT(); }
  }
}

// ---------------- fused QKV projection ----------------
__global__ __launch_bounds__(256,2) void gemm_qkv(
  const __half* __restrict__ I, const __half* __restrict__ Wt,
  const float* __restrict__ bq, const float* __restrict__ bk, const float* __restrict__ bv,
  __half* __restrict__ qq, __half* __restrict__ kk, __half* __restrict__ vv)
{
  extern __shared__ char sm[];
  const uint32_t smb = smem_u32(sm);
  const int z=blockIdx.z;
  const size_t P=(size_t)N_*D_, W=(size_t)D_*D_;
  const __half* Xp=I+(size_t)z*P;
  const __half* Wp=Wt+(size_t)z*W;
  const float* bias=(z==0)?bq:(z==1)?bk:bv;
  const float scale=(z==0)?(0.125f*1.4426950408889634f):1.0f;
  const int bm=blockIdx.y*128, bn=blockIdx.x*128;

  float acc[4][4][4];
  gemm_core(Xp,Wp,bm,bn,smb,acc);

  const int tid=threadIdx.x, lane=tid&31, wid=tid>>5;
  const int wm=wid>>2, wn=wid&3;
  const int g=lane>>2, tg=lane&3;
#pragma unroll
  for(int mi=0;mi<4;mi++){
    const int m0=bm+wm*64+mi*16+g;
#pragma unroll
    for(int ni=0;ni<4;ni++){
      const int n0=bn+wn*32+ni*8+2*tg;
      const float2 bb=*(const float2*)&bias[n0];
      float v00=(acc[mi][ni][0]+bb.x)*scale, v01=(acc[mi][ni][1]+bb.y)*scale;
      float v10=(acc[mi][ni][2]+bb.x)*scale, v11=(acc[mi][ni][3]+bb.y)*scale;
      const int h=n0>>6, hd=n0&63;
      if(z<2){
        __half* dst=(z==0)?qq:kk;
#pragma unroll
        for(int rr=0;rr<2;rr++){
          const int m=m0+rr*8, b=m>>11, s=m&(S_-1);
          const size_t idx=(((size_t)(b*H_+h)*S_)+s)*HD_+hd;
          *(uint32_t*)&dst[idx]=packh2(rr?v10:v00, rr?v11:v01);
        }
      } else {
#pragma unroll
        for(int rr=0;rr<2;rr++){
          const int m=m0+rr*8, b=m>>11, s=m&(S_-1);
#pragma unroll
          for(int e=0;e<2;e++){
            const int n=n0+e, hh=n>>6, hhd=n&63;
            float v = rr ? (e?v11:v10) : (e?v01:v00);
            vv[(((size_t)(b*H_+hh)*HD_)+hhd)*S_+s]=__float2half(v);
          }
        }
      }
    }
  }
}

// ---------------- fc GEMM (fp32 out) ----------------
__global__ __launch_bounds__(256,2) void gemm_fc(
  const __half* __restrict__ X, const __half* __restrict__ W,
  const float* __restrict__ bias, float* __restrict__ outf)
{
  extern __shared__ char sm[];
  const uint32_t smb = smem_u32(sm);
  const int bm=blockIdx.y*128, bn=blockIdx.x*128;

  float acc[4][4][4];
  gemm_core(X,W,bm,bn,smb,acc);

  const int tid=threadIdx.x, lane=tid&31, wid=tid>>5;
  const int wm=wid>>2, wn=wid&3;
  const int g=lane>>2, tg=lane&3;
#pragma unroll
  for(int mi=0;mi<4;mi++){
    const int m0=bm+wm*64+mi*16+g;
#pragma unroll
    for(int ni=0;ni<4;ni++){
      const int n0=bn+wn*32+ni*8+2*tg;
      const float2 bb=*(const float2*)&bias[n0];
      float2 w0={acc[mi][ni][0]+bb.x, acc[mi][ni][1]+bb.y};
      float2 w1={acc[mi][ni][2]+bb.x, acc[mi][ni][3]+bb.y};
      *(float2*)&outf[(size_t)m0*D_+n0]=w0;
      *(float2*)&outf[(size_t)(m0+8)*D_+n0]=w1;
    }
  }
}

// ---------------- flash attention: R13 tile shape, 2 tiles per barrier ------
// 256 thr, warp tile 32q x 64keys, Q persistent; barriers/waits halved (16).
// smem: Q[256][72] | 4 stages of { K[64][72], V[64][72] }
#define AQSZ  36864
#define ASTGn 18432
#define A_SMEM (AQSZ + 4*ASTGn)   // 110592

__global__ __launch_bounds__(256,1) void attn(
  const __half* __restrict__ Q, const __half* __restrict__ K,
  const __half* __restrict__ V, __half* __restrict__ C)
{
  extern __shared__ char sm[];
  const uint32_t smb=smem_u32(sm);
  const int tid=threadIdx.x, lane=tid&31, wid=tid>>5;
  const int bh=blockIdx.y, q0=blockIdx.x*256;

  const uint32_t arow=(lane&7)+8*((lane>>3)&1), akof=(lane>>4)*8;
  const uint32_t brow=lane&7, bkof=(lane>>3)*8;
  const uint32_t ones2[2]={0x3C003C00u,0x3C003C00u};

  auto ldt=[&](int i,int s){
    const __half* kp=K+((size_t)bh*S_+i*64)*HD_;
    const __half* vp=V+(size_t)bh*HD_*S_+i*64;
    const uint32_t sb=smb+AQSZ+s*ASTGn;
#pragma unroll
    for(int t=tid;t<512;t+=256){
      int r=t>>3, sg=t&7;
      cpa16(sb+r*144+sg*16,      kp+(size_t)r*HD_+sg*8);
      cpa16(sb+9216+r*144+sg*16, vp+(size_t)r*S_+sg*8);
    }
  };

  // one 64-key tile: S' -> P=2^S' -> lacc,O  (identical math/order to R13)
  auto tile=[&](uint32_t base, uint32_t qf[2][4][4],
                float oacc[2][8][4], float lacc[2][4]){
    float sacc[2][8][4];
#pragma unroll
    for(int mi=0;mi<2;mi++)
#pragma unroll
      for(int ni=0;ni<8;ni++)
#pragma unroll
        for(int r=0;r<4;r++) sacc[mi][ni][r]=0.f;
#pragma unroll
    for(int kp=0;kp<2;kp++){
#pragma unroll
      for(int ni=0;ni<8;ni++){
        uint32_t ad=base+(ni*8+brow)*144+(kp*32+bkof)*2;
        uint32_t kf[4]; ldsm4(kf,ad);
#pragma unroll
        for(int mi=0;mi<2;mi++){
          mma_f16(sacc[mi][ni], qf[mi][2*kp],   &kf[0]);
          mma_f16(sacc[mi][ni], qf[mi][2*kp+1], &kf[2]);
        }
      }
    }
#pragma unroll
    for(int kp=0;kp<2;kp++){
      uint32_t p0[2][4], p1[2][4];
#pragma unroll
      for(int mi=0;mi<2;mi++){
        const int j0=4*kp;
        p0[mi][0]=ex2h2(packh2(sacc[mi][j0  ][0],sacc[mi][j0  ][1]));
        p0[mi][1]=ex2h2(packh2(sacc[mi][j0  ][2],sacc[mi][j0  ][3]));
        p0[mi][2]=ex2h2(packh2(sacc[mi][j0+1][0],sacc[mi][j0+1][1]));
        p0[mi][3]=ex2h2(packh2(sacc[mi][j0+1][2],sacc[mi][j0+1][3]));
        p1[mi][0]=ex2h2(packh2(sacc[mi][j0+2][0],sacc[mi][j0+2][1]));
        p1[mi][1]=ex2h2(packh2(sacc[mi][j0+2][2],sacc[mi][j0+2][3]));
        p1[mi][2]=ex2h2(packh2(sacc[mi][j0+3][0],sacc[mi][j0+3][1]));
        p1[mi][3]=ex2h2(packh2(sacc[mi][j0+3][2],sacc[mi][j0+3][3]));
        mma_f16(lacc[mi], p0[mi], ones2);
        mma_f16(lacc[mi], p1[mi], ones2);
      }
#pragma unroll
      for(int ni=0;ni<8;ni++){
        uint32_t ad=base+9216+(ni*8+brow)*144+(kp*32+bkof)*2;
        uint32_t vf[4]; ldsm4(vf,ad);
#pragma unroll
        for(int mi=0;mi<2;mi++){
          mma_f16(oacc[mi][ni], p0[mi], &vf[0]);
          mma_f16(oacc[mi][ni], p1[mi], &vf[2]);
        }
      }
    }
  };

  // prologue: Q (256 rows, persistent) + tile groups {0,1}, {2,3}
  {
    const __half* qp=Q+((size_t)bh*S_+q0)*HD_;
#pragma unroll
    for(int t=tid;t<2048;t+=256){
      int r=t>>3, sg=t&7;
      cpa16(smb+r*144+sg*16, qp+(size_t)r*HD_+sg*8);
    }
    CPA_COMMIT();
  }
  ldt(0,0); ldt(1,1); CPA_COMMIT();
  ldt(2,2); ldt(3,3); CPA_COMMIT();

  // persistent Q fragments (after Q group completes: 2 groups outstanding after it)
  CPA_WAIT(2);
  __syncthreads();
  uint32_t qf[2][4][4];
#pragma unroll
  for(int mi=0;mi<2;mi++)
#pragma unroll
    for(int ks=0;ks<4;ks++){
      uint32_t ad=smb+(wid*32+mi*16+arow)*144+(ks*16+akof)*2;
      ldsm4(qf[mi][ks],ad);
    }

  float oacc[2][8][4];
#pragma unroll
  for(int mi=0;mi<2;mi++)
#pragma unroll
    for(int i=0;i<8;i++)
#pragma unroll
      for(int r=0;r<4;r++) oacc[mi][i][r]=0.f;
  float lacc[2][4]={{0.f,0.f,0.f,0.f},{0.f,0.f,0.f,0.f}};

  // 16 iterations, 2 tiles each — one barrier + one wait per pair
  for(int it=0;it<16;it++){
    if(it<15){ CPA_WAIT(1); } else { CPA_WAIT(0); }
    __syncthreads();
    const int a=2*it;
    tile(smb+AQSZ+(a&3)*ASTGn,     qf, oacc, lacc);
    tile(smb+AQSZ+((a+1)&3)*ASTGn, qf, oacc, lacc);
    if(a+4<32){ ldt(a+4,(a+4)&3); ldt(a+5,(a+5)&3); CPA_COMMIT(); }
  }

  const int g=lane>>2, tg=lane&3;
  const int b=bh>>4, h=bh&15;
#pragma unroll
  for(int mi=0;mi<2;mi++){
    const float inv0=1.f/lacc[mi][0], inv1=1.f/lacc[mi][2];
    const int r0=q0+wid*32+mi*16+g;
#pragma unroll
    for(int ni=0;ni<8;ni++){
      const int d=ni*8+2*tg;
      size_t idx=((size_t)(b*S_+r0))*D_+h*HD_+d;
      *(uint32_t*)&C[idx]=packh2(oacc[mi][ni][0]*inv0, oacc[mi][ni][1]*inv0);
      idx=((size_t)(b*S_+r0+8))*D_+h*HD_+d;
      *(uint32_t*)&C[idx]=packh2(oacc[mi][ni][2]*inv1, oacc[mi][ni][3]*inv1);
    }
  }
}

// ---------------- launch ----------------
extern "C" void kernel_launch(void* const* d_in, const int* in_sizes, int n_in,
                              void* d_out, int out_size)
{
  const float* query=(const float*)d_in[0];
  const float* key  =(const float*)d_in[1];
  const float* value=(const float*)d_in[2];
  const float* w_q=(const float*)d_in[3];  const float* b_q=(const float*)d_in[4];
  const float* w_k=(const float*)d_in[5];  const float* b_k=(const float*)d_in[6];
  const float* w_v=(const float*)d_in[7];  const float* b_v=(const float*)d_in[8];
  const float* w_fc=(const float*)d_in[9]; const float* b_fc=(const float*)d_in[10];
  float* out=(float*)d_out;

  __half *pI,*pW,*pQ,*pK,*pV,*pC;
  cudaGetSymbolAddress((void**)&pI,g_I);
  cudaGetSymbolAddress((void**)&pW,g_W);
  cudaGetSymbolAddress((void**)&pQ,g_Q); cudaGetSymbolAddress((void**)&pK,g_K);
  cudaGetSymbolAddress((void**)&pV,g_V); cudaGetSymbolAddress((void**)&pC,g_C);

  cudaFuncSetAttribute(gemm_qkv,cudaFuncAttributeMaxDynamicSharedMemorySize,G_SMEM);
  cudaFuncSetAttribute(gemm_fc, cudaFuncAttributeMaxDynamicSharedMemorySize,G_SMEM);
  cudaFuncSetAttribute(attn,    cudaFuncAttributeMaxDynamicSharedMemorySize,A_SMEM);

  cvt_act<<<dim3((N_*D_/2)/256,3),256>>>(query,key,value,pI);
  wsplit<<<dim3(32,32,4),dim3(32,8)>>>(w_q,w_k,w_v,w_fc,pW);

  const size_t W=(size_t)D_*D_;
  gemm_qkv<<<dim3(8,32,3),256,G_SMEM>>>(pI,pW,b_q,b_k,b_v,pQ,pK,pV);

  attn<<<dim3(8,32),256,A_SMEM>>>(pQ,pK,pV,pC);

  gemm_fc<<<dim3(8,32),256,G_SMEM>>>(pC,pW+3*W,b_fc,out);
}